// round 1
// baseline (speedup 1.0000x reference)
#include <cuda_runtime.h>

// OU scan via scaled prefix sum:
//   x[b,i,d] = e^{-th*t_i} * ( x0[b,d] + sum_{j<=i} e^{th*t_j} * sqrt(1-c_j^2) * z[b,j,d] )
// with c_j = exp(-th*dt_j), th = 0.5. Single-pass decoupled-lookback chunked scan.

namespace {
constexpr int   B     = 64;
constexpr int   S     = 4096;
constexpr int   D     = 256;
constexpr int   TS    = 64;          // timesteps per chunk
constexpr int   K     = S / TS;      // 64 chunks per batch
constexpr int   NB    = B * K;       // 4096 blocks
constexpr int   SUBS  = 4;           // s-subtiles per block (256 thr / 64 d4-lanes)
constexpr int   SLEN  = TS / SUBS;   // 16 sequential steps per thread
constexpr int   D4    = D / 4;       // 64 float4 lanes across D
constexpr float THETA = 0.5f;
}

// Scratch (static device globals; no allocation anywhere)
__device__ float4 gAgg [NB * D4];    // per-(b,chunk) aggregate, vector over d
__device__ float4 gIncl[NB * D4];    // per-(b,chunk) inclusive prefix
__device__ int    gFlag[NB];         // 0=invalid, 1=aggregate ready, 2=inclusive ready

__global__ void init_flags_kernel() {
    int i = blockIdx.x * blockDim.x + threadIdx.x;
    if (i < NB) gFlag[i] = 0;
}

__global__ __launch_bounds__(256) void ou_scan_kernel(
    const float* __restrict__ t,
    const float* __restrict__ x0,
    const float* __restrict__ z,
    float*       __restrict__ out)
{
    __shared__ float  su  [TS];        // e^{th*t_s} * sqrt(1 - c_s^2)
    __shared__ float  sinv[TS];        // e^{-th*t_s}
    __shared__ float4 shPart[SUBS * D4];
    __shared__ float4 shExcl[D4];
    __shared__ int    sflag;

    const int bx   = blockIdx.x;
    const int b    = bx / K;
    const int k    = bx - b * K;
    const int s0   = k * TS;
    const int tid  = threadIdx.x;
    const int sub  = tid >> 6;         // 0..3 : which s-subtile
    const int lane = tid & 63;         // 0..63: which float4 of D

    // --- per-step scale factors (shared, once per block) ---
    if (tid < TS) {
        int   s  = s0 + tid;
        float tc = t[b * S + s];
        float tp = (s == 0) ? 0.0f : t[b * S + s - 1];
        float c  = expf(-THETA * (tc - tp));
        float sq = sqrtf(fmaxf(1.0f - c * c, 0.0f));
        su[tid]   = expf(THETA * tc) * sq;
        sinv[tid] = expf(-THETA * tc);
    }
    __syncthreads();

    const float4* zp = reinterpret_cast<const float4*>(z)
                     + (size_t)(b * S + s0 + sub * SLEN) * D4 + lane;
    float4* op       = reinterpret_cast<float4*>(out)
                     + (size_t)(b * S + s0 + sub * SLEN) * D4 + lane;

    // --- Phase A: partial sums of u = su[s]*z over this sub's SLEN steps ---
    float4 p = make_float4(0.f, 0.f, 0.f, 0.f);
    #pragma unroll
    for (int i = 0; i < SLEN; ++i) {
        float4 zv = zp[(size_t)i * D4];
        float  sc = su[sub * SLEN + i];
        p.x = fmaf(sc, zv.x, p.x);
        p.y = fmaf(sc, zv.y, p.y);
        p.z = fmaf(sc, zv.z, p.z);
        p.w = fmaf(sc, zv.w, p.w);
    }
    shPart[sub * D4 + lane] = p;
    __syncthreads();

    // --- aggregate across subs, publish ---
    float4 agg = make_float4(0.f, 0.f, 0.f, 0.f);
    if (tid < D4) {
        float4 a0 = shPart[tid];
        float4 a1 = shPart[D4 + tid];
        float4 a2 = shPart[2 * D4 + tid];
        float4 a3 = shPart[3 * D4 + tid];
        agg.x = (a0.x + a1.x) + (a2.x + a3.x);
        agg.y = (a0.y + a1.y) + (a2.y + a3.y);
        agg.z = (a0.z + a1.z) + (a2.z + a3.z);
        agg.w = (a0.w + a1.w) + (a2.w + a3.w);
        gAgg[bx * D4 + tid] = agg;
    }
    __threadfence();
    __syncthreads();
    if (tid == 0) atomicExch(&gFlag[bx], 1);

    // --- decoupled lookback: exclusive prefix over predecessor chunks ---
    float4 excl = make_float4(0.f, 0.f, 0.f, 0.f);
    for (int j = k - 1; j >= 0; --j) {
        __syncthreads();               // protect sflag reuse across iterations
        if (tid == 0) {
            int f;
            while ((f = atomicAdd(&gFlag[b * K + j], 0)) == 0) __nanosleep(64);
            __threadfence();           // acquire: order value loads after flag
            sflag = f;
        }
        __syncthreads();
        int f = sflag;
        if (tid < D4) {
            int gi = (b * K + j) * D4 + tid;
            float4 v = (f == 2) ? gIncl[gi] : gAgg[gi];
            excl.x += v.x; excl.y += v.y; excl.z += v.z; excl.w += v.w;
        }
        if (f == 2) break;             // uniform across block
    }

    if (tid < D4) {
        shExcl[tid] = excl;
        if (k > 0 && k < K - 1) {      // k==0: agg==inclusive already published
            float4 inc = make_float4(excl.x + agg.x, excl.y + agg.y,
                                     excl.z + agg.z, excl.w + agg.w);
            gIncl[bx * D4 + tid] = inc;
        }
    }
    __threadfence();
    __syncthreads();
    if (tid == 0 && k > 0 && k < K - 1) atomicExch(&gFlag[bx], 2);

    // --- Phase B: stream final outputs (z tile re-read, expected L2-hot) ---
    float4 run = shExcl[lane];
    for (int s2 = 0; s2 < sub; ++s2) { // intra-block prefix over earlier subs
        float4 pp = shPart[s2 * D4 + lane];
        run.x += pp.x; run.y += pp.y; run.z += pp.z; run.w += pp.w;
    }
    const float4 x04 = reinterpret_cast<const float4*>(x0)[b * D4 + lane];

    #pragma unroll
    for (int i = 0; i < SLEN; ++i) {
        int    si = sub * SLEN + i;
        float4 zv = zp[(size_t)i * D4];
        float  sc = su[si];
        run.x = fmaf(sc, zv.x, run.x);
        run.y = fmaf(sc, zv.y, run.y);
        run.z = fmaf(sc, zv.z, run.z);
        run.w = fmaf(sc, zv.w, run.w);
        float e = sinv[si];
        float4 o;
        o.x = e * (x04.x + run.x);
        o.y = e * (x04.y + run.y);
        o.z = e * (x04.z + run.z);
        o.w = e * (x04.w + run.w);
        op[(size_t)i * D4] = o;
    }
}

extern "C" void kernel_launch(void* const* d_in, const int* in_sizes, int n_in,
                              void* d_out, int out_size) {
    (void)in_sizes; (void)n_in; (void)out_size;
    const float* t  = (const float*)d_in[0];
    const float* x0 = (const float*)d_in[1];
    const float* z  = (const float*)d_in[2];
    float* out      = (float*)d_out;

    init_flags_kernel<<<(NB + 255) / 256, 256>>>();
    ou_scan_kernel<<<NB, 256>>>(t, x0, z, out);
}

// round 2
// speedup vs baseline: 1.4149x; 1.4149x over previous
#include <cuda_runtime.h>

// OU scan via scaled prefix sum:
//   x[b,i,d] = e^{-th*t_i} * ( x0[b,d] + sum_{j<=i} e^{th*t_j} * sqrt(1-c_j^2) * z[b,j,d] )
// Single-pass decoupled lookback, CHUNK-MAJOR grid order so predecessors are
// scheduled ~B blocks earlier (inclusive prefix almost always ready), and the
// z tile is kept register-resident across the lookback (no L2 re-read).

namespace {
constexpr int   B     = 64;
constexpr int   S     = 4096;
constexpr int   D     = 256;
constexpr int   TS    = 64;          // timesteps per chunk
constexpr int   K     = S / TS;      // 64 chunks per batch
constexpr int   NB    = B * K;       // 4096 blocks
constexpr int   SUBS  = 4;           // s-subtiles per block
constexpr int   SLEN  = TS / SUBS;   // 16 steps per thread
constexpr int   D4    = D / 4;       // 64 float4 lanes across D
constexpr float THETA = 0.5f;
}

__device__ float4 gAgg [NB * D4];
__device__ float4 gIncl[NB * D4];
__device__ int    gFlag[NB];         // 0=invalid, 1=aggregate, 2=inclusive

__global__ void init_flags_kernel() {
    int i = blockIdx.x * blockDim.x + threadIdx.x;
    if (i < NB) gFlag[i] = 0;
}

__global__ __launch_bounds__(256, 2) void ou_scan_kernel(
    const float* __restrict__ t,
    const float* __restrict__ x0,
    const float* __restrict__ z,
    float*       __restrict__ out)
{
    __shared__ float  su  [TS];
    __shared__ float  sinv[TS];
    __shared__ float4 shPart[SUBS * D4];
    __shared__ float4 shExcl[D4];
    __shared__ int    sflag;

    const int bx   = blockIdx.x;
    const int k    = bx / B;           // chunk-major: chunk index varies slowest
    const int b    = bx - k * B;
    const int cid  = b * K + k;        // storage id for (batch, chunk)
    const int s0   = k * TS;
    const int tid  = threadIdx.x;
    const int sub  = tid >> 6;
    const int lane = tid & 63;

    if (tid < TS) {
        int   s  = s0 + tid;
        float tc = t[b * S + s];
        float tp = (s == 0) ? 0.0f : t[b * S + s - 1];
        float c  = expf(-THETA * (tc - tp));
        float sq = sqrtf(fmaxf(1.0f - c * c, 0.0f));
        su[tid]   = expf(THETA * tc) * sq;
        sinv[tid] = expf(-THETA * tc);
    }
    __syncthreads();

    const float4* zp = reinterpret_cast<const float4*>(z)
                     + (size_t)(b * S + s0 + sub * SLEN) * D4 + lane;
    float4* op       = reinterpret_cast<float4*>(out)
                     + (size_t)(b * S + s0 + sub * SLEN) * D4 + lane;

    // --- load z tile once, keep in registers (streaming: no reuse) ---
    float4 zv[SLEN];
    #pragma unroll
    for (int i = 0; i < SLEN; ++i)
        zv[i] = __ldcs(&zp[(size_t)i * D4]);

    // --- partial sums of u = su[s]*z over this sub's steps ---
    float4 p = make_float4(0.f, 0.f, 0.f, 0.f);
    #pragma unroll
    for (int i = 0; i < SLEN; ++i) {
        float sc = su[sub * SLEN + i];
        p.x = fmaf(sc, zv[i].x, p.x);
        p.y = fmaf(sc, zv[i].y, p.y);
        p.z = fmaf(sc, zv[i].z, p.z);
        p.w = fmaf(sc, zv[i].w, p.w);
    }
    shPart[sub * D4 + lane] = p;
    __syncthreads();

    // --- block aggregate; chunk 0 publishes INCLUSIVE (flag=2) directly ---
    float4 agg = make_float4(0.f, 0.f, 0.f, 0.f);
    if (tid < D4) {
        float4 a0 = shPart[tid];
        float4 a1 = shPart[D4 + tid];
        float4 a2 = shPart[2 * D4 + tid];
        float4 a3 = shPart[3 * D4 + tid];
        agg.x = (a0.x + a1.x) + (a2.x + a3.x);
        agg.y = (a0.y + a1.y) + (a2.y + a3.y);
        agg.z = (a0.z + a1.z) + (a2.z + a3.z);
        agg.w = (a0.w + a1.w) + (a2.w + a3.w);
        if (k == 0) gIncl[cid * D4 + tid] = agg;
        else        gAgg [cid * D4 + tid] = agg;
    }
    __threadfence();
    __syncthreads();
    if (tid == 0) atomicExch(&gFlag[cid], (k == 0) ? 2 : 1);

    // --- lookback (short: predecessor is ~B blocks earlier in schedule) ---
    if (k > 0) {
        float4 excl = make_float4(0.f, 0.f, 0.f, 0.f);
        for (int j = k - 1; ; --j) {
            __syncthreads();
            if (tid == 0) {
                int f;
                while ((f = atomicAdd(&gFlag[b * K + j], 0)) == 0) __nanosleep(64);
                __threadfence();
                sflag = f;
            }
            __syncthreads();
            int f = sflag;
            if (tid < D4) {
                int gi = (b * K + j) * D4 + tid;
                float4 v = (f == 2) ? gIncl[gi] : gAgg[gi];
                excl.x += v.x; excl.y += v.y; excl.z += v.z; excl.w += v.w;
            }
            if (f == 2) break;
        }
        if (tid < D4) {
            shExcl[tid] = excl;
            float4 inc = make_float4(excl.x + agg.x, excl.y + agg.y,
                                     excl.z + agg.z, excl.w + agg.w);
            gIncl[cid * D4 + tid] = inc;
        }
        __threadfence();
        __syncthreads();
        if (tid == 0) atomicExch(&gFlag[cid], 2);
    } else {
        if (tid < D4) shExcl[tid] = make_float4(0.f, 0.f, 0.f, 0.f);
        __syncthreads();
    }

    // --- final outputs straight from registers ---
    float4 run = shExcl[lane];
    #pragma unroll
    for (int s2 = 0; s2 < SUBS - 1; ++s2) {
        if (s2 < sub) {
            float4 pp = shPart[s2 * D4 + lane];
            run.x += pp.x; run.y += pp.y; run.z += pp.z; run.w += pp.w;
        }
    }
    const float4 x04 = reinterpret_cast<const float4*>(x0)[b * D4 + lane];

    #pragma unroll
    for (int i = 0; i < SLEN; ++i) {
        int   si = sub * SLEN + i;
        float sc = su[si];
        run.x = fmaf(sc, zv[i].x, run.x);
        run.y = fmaf(sc, zv[i].y, run.y);
        run.z = fmaf(sc, zv[i].z, run.z);
        run.w = fmaf(sc, zv[i].w, run.w);
        float e = sinv[si];
        float4 o;
        o.x = e * (x04.x + run.x);
        o.y = e * (x04.y + run.y);
        o.z = e * (x04.z + run.z);
        o.w = e * (x04.w + run.w);
        __stcs(&op[(size_t)i * D4], o);
    }
}

extern "C" void kernel_launch(void* const* d_in, const int* in_sizes, int n_in,
                              void* d_out, int out_size) {
    (void)in_sizes; (void)n_in; (void)out_size;
    const float* t  = (const float*)d_in[0];
    const float* x0 = (const float*)d_in[1];
    const float* z  = (const float*)d_in[2];
    float* out      = (float*)d_out;

    init_flags_kernel<<<(NB + 255) / 256, 256>>>();
    ou_scan_kernel<<<NB, 256>>>(t, x0, z, out);
}

// round 3
// speedup vs baseline: 1.7145x; 1.2117x over previous
#include <cuda_runtime.h>

// OU scan via scaled prefix sum:
//   x[b,i,d] = e^{-th*t_i} * ( x0[b,d] + sum_{j<=i} e^{th*t_j} * sqrt(1-c_j^2) * z[b,j,d] )
// Single-pass decoupled lookback, chunk-major grid order (predecessor ~B blocks
// earlier in schedule -> inclusive usually ready). z re-read from L1/L2 in
// Phase B instead of register-resident tile, trading L2 traffic for occupancy.

namespace {
constexpr int   B     = 64;
constexpr int   S     = 4096;
constexpr int   D     = 256;
constexpr int   TS    = 64;          // timesteps per chunk
constexpr int   K     = S / TS;      // 64 chunks per batch
constexpr int   NB    = B * K;       // 4096 blocks
constexpr int   SUBS  = 4;           // s-subtiles per block
constexpr int   SLEN  = TS / SUBS;   // 16 steps per thread
constexpr int   D4    = D / 4;       // 64 float4 lanes across D
constexpr float THETA = 0.5f;
}

__device__ float4 gAgg [NB * D4];
__device__ float4 gIncl[NB * D4];
__device__ int    gFlag[NB];         // 0=invalid, 1=aggregate, 2=inclusive

__global__ void init_flags_kernel() {
    int i = blockIdx.x * blockDim.x + threadIdx.x;
    if (i < NB) gFlag[i] = 0;
}

__global__ __launch_bounds__(256) void ou_scan_kernel(
    const float* __restrict__ t,
    const float* __restrict__ x0,
    const float* __restrict__ z,
    float*       __restrict__ out)
{
    __shared__ float  su  [TS];
    __shared__ float  sinv[TS];
    __shared__ float4 shPart[SUBS * D4];
    __shared__ float4 shExcl[D4];
    __shared__ int    sflag;

    const int bx   = blockIdx.x;
    const int k    = bx / B;           // chunk-major: chunk index varies slowest
    const int b    = bx - k * B;
    const int cid  = b * K + k;        // storage id for (batch, chunk)
    const int s0   = k * TS;
    const int tid  = threadIdx.x;
    const int sub  = tid >> 6;
    const int lane = tid & 63;

    if (tid < TS) {
        int   s  = s0 + tid;
        float tc = t[b * S + s];
        float tp = (s == 0) ? 0.0f : t[b * S + s - 1];
        float c  = expf(-THETA * (tc - tp));
        float sq = sqrtf(fmaxf(1.0f - c * c, 0.0f));
        su[tid]   = expf(THETA * tc) * sq;
        sinv[tid] = expf(-THETA * tc);
    }
    __syncthreads();

    const float4* zp = reinterpret_cast<const float4*>(z)
                     + (size_t)(b * S + s0 + sub * SLEN) * D4 + lane;
    float4* op       = reinterpret_cast<float4*>(out)
                     + (size_t)(b * S + s0 + sub * SLEN) * D4 + lane;

    // --- Phase A: partial sums of u = su[s]*z (first z read, cache in L1/L2) ---
    float4 p = make_float4(0.f, 0.f, 0.f, 0.f);
    #pragma unroll 4
    for (int i = 0; i < SLEN; ++i) {
        float4 zv = __ldg(&zp[(size_t)i * D4]);
        float  sc = su[sub * SLEN + i];
        p.x = fmaf(sc, zv.x, p.x);
        p.y = fmaf(sc, zv.y, p.y);
        p.z = fmaf(sc, zv.z, p.z);
        p.w = fmaf(sc, zv.w, p.w);
    }
    shPart[sub * D4 + lane] = p;
    __syncthreads();

    // --- block aggregate; chunk 0 publishes INCLUSIVE (flag=2) directly ---
    float4 agg = make_float4(0.f, 0.f, 0.f, 0.f);
    if (tid < D4) {
        float4 a0 = shPart[tid];
        float4 a1 = shPart[D4 + tid];
        float4 a2 = shPart[2 * D4 + tid];
        float4 a3 = shPart[3 * D4 + tid];
        agg.x = (a0.x + a1.x) + (a2.x + a3.x);
        agg.y = (a0.y + a1.y) + (a2.y + a3.y);
        agg.z = (a0.z + a1.z) + (a2.z + a3.z);
        agg.w = (a0.w + a1.w) + (a2.w + a3.w);
        if (k == 0) gIncl[cid * D4 + tid] = agg;
        else        gAgg [cid * D4 + tid] = agg;
    }
    __threadfence();
    __syncthreads();
    if (tid == 0) atomicExch(&gFlag[cid], (k == 0) ? 2 : 1);

    // --- lookback (short: predecessor is ~B blocks earlier in schedule) ---
    if (k > 0) {
        float4 excl = make_float4(0.f, 0.f, 0.f, 0.f);
        for (int j = k - 1; ; --j) {
            __syncthreads();
            if (tid == 0) {
                int f;
                while ((f = atomicAdd(&gFlag[b * K + j], 0)) == 0) __nanosleep(64);
                __threadfence();
                sflag = f;
            }
            __syncthreads();
            int f = sflag;
            if (tid < D4) {
                int gi = (b * K + j) * D4 + tid;
                float4 v = (f == 2) ? gIncl[gi] : gAgg[gi];
                excl.x += v.x; excl.y += v.y; excl.z += v.z; excl.w += v.w;
            }
            if (f == 2) break;
        }
        if (tid < D4) {
            shExcl[tid] = excl;
            float4 inc = make_float4(excl.x + agg.x, excl.y + agg.y,
                                     excl.z + agg.z, excl.w + agg.w);
            gIncl[cid * D4 + tid] = inc;
        }
        __threadfence();
        __syncthreads();
        if (tid == 0) atomicExch(&gFlag[cid], 2);
    } else {
        if (tid < D4) shExcl[tid] = make_float4(0.f, 0.f, 0.f, 0.f);
        __syncthreads();
    }

    // --- Phase B: re-read z (L1/L2-hot) and stream outputs ---
    float4 run = shExcl[lane];
    #pragma unroll
    for (int s2 = 0; s2 < SUBS - 1; ++s2) {
        if (s2 < sub) {
            float4 pp = shPart[s2 * D4 + lane];
            run.x += pp.x; run.y += pp.y; run.z += pp.z; run.w += pp.w;
        }
    }
    const float4 x04 = reinterpret_cast<const float4*>(x0)[b * D4 + lane];

    #pragma unroll 4
    for (int i = 0; i < SLEN; ++i) {
        int    si = sub * SLEN + i;
        float4 zv = __ldg(&zp[(size_t)i * D4]);
        float  sc = su[si];
        run.x = fmaf(sc, zv.x, run.x);
        run.y = fmaf(sc, zv.y, run.y);
        run.z = fmaf(sc, zv.z, run.z);
        run.w = fmaf(sc, zv.w, run.w);
        float e = sinv[si];
        float4 o;
        o.x = e * (x04.x + run.x);
        o.y = e * (x04.y + run.y);
        o.z = e * (x04.z + run.z);
        o.w = e * (x04.w + run.w);
        __stcs(&op[(size_t)i * D4], o);
    }
}

extern "C" void kernel_launch(void* const* d_in, const int* in_sizes, int n_in,
                              void* d_out, int out_size) {
    (void)in_sizes; (void)n_in; (void)out_size;
    const float* t  = (const float*)d_in[0];
    const float* x0 = (const float*)d_in[1];
    const float* z  = (const float*)d_in[2];
    float* out      = (float*)d_out;

    init_flags_kernel<<<(NB + 255) / 256, 256>>>();
    ou_scan_kernel<<<NB, 256>>>(t, x0, z, out);
}

// round 4
// speedup vs baseline: 1.8287x; 1.0666x over previous
#include <cuda_runtime.h>

// OU scan via scaled prefix sum:
//   x[b,i,d] = e^{-th*t_i} * ( x0[b,d] + sum_{j<=i} e^{th*t_j} * sqrt(1-c_j^2) * z[b,j,d] )
// Single-pass decoupled lookback, chunk-major grid. The scaled tile u = su*z
// is stashed in SMEM during Phase A, so z is read from DRAM exactly once
// (pure streaming: __ldcs / __stcs). Flag protocol uses acquire/release PTX
// instead of __threadfence.

namespace {
constexpr int   B     = 64;
constexpr int   S     = 4096;
constexpr int   D     = 256;
constexpr int   TS    = 32;          // timesteps per chunk
constexpr int   K     = S / TS;      // 128 chunks per batch
constexpr int   NB    = B * K;       // 8192 blocks
constexpr int   SUBS  = 4;           // s-subtiles per block
constexpr int   SLEN  = TS / SUBS;   // 8 steps per thread
constexpr int   D4    = D / 4;       // 64 float4 lanes across D
constexpr float THETA = 0.5f;
}

__device__ float4 gAgg [NB * D4];
__device__ float4 gIncl[NB * D4];
__device__ int    gFlag[NB];         // 0=invalid, 1=aggregate, 2=inclusive

__device__ __forceinline__ int ld_acquire_gpu(const int* p) {
    int v;
    asm volatile("ld.global.acquire.gpu.b32 %0, [%1];" : "=r"(v) : "l"(p) : "memory");
    return v;
}
__device__ __forceinline__ void st_release_gpu(int* p, int v) {
    asm volatile("st.global.release.gpu.b32 [%0], %1;" :: "l"(p), "r"(v) : "memory");
}

__global__ void init_flags_kernel() {
    int i = blockIdx.x * blockDim.x + threadIdx.x;
    if (i < NB) gFlag[i] = 0;
}

__global__ __launch_bounds__(256) void ou_scan_kernel(
    const float* __restrict__ t,
    const float* __restrict__ x0,
    const float* __restrict__ z,
    float*       __restrict__ out)
{
    __shared__ float  su  [TS];
    __shared__ float  sinv[TS];
    __shared__ float4 shU  [TS * D4];      // 32 KB: scaled tile u = su*z
    __shared__ float4 shPart[SUBS * D4];   // per-sub partials; [3] reused as excl
    __shared__ int    sflag;

    const int bx   = blockIdx.x;
    const int k    = bx / B;           // chunk-major
    const int b    = bx - k * B;
    const int cid  = b * K + k;
    const int s0   = k * TS;
    const int tid  = threadIdx.x;
    const int sub  = tid >> 6;
    const int lane = tid & 63;

    if (tid < TS) {
        int   s  = s0 + tid;
        float tc = t[b * S + s];
        float tp = (s == 0) ? 0.0f : t[b * S + s - 1];
        float c  = expf(-THETA * (tc - tp));
        float sq = sqrtf(fmaxf(1.0f - c * c, 0.0f));
        su[tid]   = expf(THETA * tc) * sq;
        sinv[tid] = expf(-THETA * tc);
    }
    __syncthreads();

    const float4* zp = reinterpret_cast<const float4*>(z)
                     + (size_t)(b * S + s0 + sub * SLEN) * D4 + lane;
    float4* op       = reinterpret_cast<float4*>(out)
                     + (size_t)(b * S + s0 + sub * SLEN) * D4 + lane;

    // --- Phase A: single streaming read of z; stash u = su*z in SMEM ---
    float4 p = make_float4(0.f, 0.f, 0.f, 0.f);
    #pragma unroll
    for (int i = 0; i < SLEN; ++i) {
        float4 zv = __ldcs(&zp[(size_t)i * D4]);
        float  sc = su[sub * SLEN + i];
        float4 u;
        u.x = sc * zv.x; u.y = sc * zv.y; u.z = sc * zv.z; u.w = sc * zv.w;
        shU[(sub * SLEN + i) * D4 + lane] = u;
        p.x += u.x; p.y += u.y; p.z += u.z; p.w += u.w;
    }
    shPart[sub * D4 + lane] = p;
    __syncthreads();

    // --- block aggregate; chunk 0 publishes INCLUSIVE (flag=2) directly ---
    float4 agg = make_float4(0.f, 0.f, 0.f, 0.f);
    if (tid < D4) {
        float4 a0 = shPart[tid];
        float4 a1 = shPart[D4 + tid];
        float4 a2 = shPart[2 * D4 + tid];
        float4 a3 = shPart[3 * D4 + tid];
        agg.x = (a0.x + a1.x) + (a2.x + a3.x);
        agg.y = (a0.y + a1.y) + (a2.y + a3.y);
        agg.z = (a0.z + a1.z) + (a2.z + a3.z);
        agg.w = (a0.w + a1.w) + (a2.w + a3.w);
        if (k == 0) gIncl[cid * D4 + tid] = agg;
        else        gAgg [cid * D4 + tid] = agg;
    }
    __syncthreads();                      // g-writes done CTA-wide
    if (tid == 0) st_release_gpu(&gFlag[cid], (k == 0) ? 2 : 1);

    // --- lookback ---
    if (k > 0) {
        float4 excl = make_float4(0.f, 0.f, 0.f, 0.f);
        int j = k - 1;
        for (;;) {
            if (tid == 0) {
                int f;
                while ((f = ld_acquire_gpu(&gFlag[b * K + j])) == 0) __nanosleep(64);
                sflag = f;
            }
            __syncthreads();
            int f = sflag;
            if (tid < D4) {
                int gi = (b * K + j) * D4 + tid;
                float4 v = (f == 2) ? gIncl[gi] : gAgg[gi];
                excl.x += v.x; excl.y += v.y; excl.z += v.z; excl.w += v.w;
            }
            if (f == 2) break;
            --j;
            __syncthreads();              // before sflag is rewritten
        }
        if (tid < D4) {
            gIncl[cid * D4 + tid] = make_float4(excl.x + agg.x, excl.y + agg.y,
                                                excl.z + agg.z, excl.w + agg.w);
            shPart[3 * D4 + tid] = excl;  // sub-3 partial no longer needed
        }
        __syncthreads();
        if (tid == 0) st_release_gpu(&gFlag[cid], 2);
    } else {
        if (tid < D4) shPart[3 * D4 + tid] = make_float4(0.f, 0.f, 0.f, 0.f);
        __syncthreads();
    }

    // --- Phase B: outputs from SMEM tile (no global re-read) ---
    float4 run = shPart[3 * D4 + lane];   // exclusive chunk prefix
    #pragma unroll
    for (int s2 = 0; s2 < SUBS - 1; ++s2) {
        if (s2 < sub) {
            float4 pp = shPart[s2 * D4 + lane];
            run.x += pp.x; run.y += pp.y; run.z += pp.z; run.w += pp.w;
        }
    }
    const float4 x04 = reinterpret_cast<const float4*>(x0)[b * D4 + lane];

    #pragma unroll
    for (int i = 0; i < SLEN; ++i) {
        int    si = sub * SLEN + i;
        float4 u  = shU[si * D4 + lane];
        run.x += u.x; run.y += u.y; run.z += u.z; run.w += u.w;
        float e = sinv[si];
        float4 o;
        o.x = e * (x04.x + run.x);
        o.y = e * (x04.y + run.y);
        o.z = e * (x04.z + run.z);
        o.w = e * (x04.w + run.w);
        __stcs(&op[(size_t)i * D4], o);
    }
}

extern "C" void kernel_launch(void* const* d_in, const int* in_sizes, int n_in,
                              void* d_out, int out_size) {
    (void)in_sizes; (void)n_in; (void)out_size;
    const float* t  = (const float*)d_in[0];
    const float* x0 = (const float*)d_in[1];
    const float* z  = (const float*)d_in[2];
    float* out      = (float*)d_out;

    init_flags_kernel<<<(NB + 255) / 256, 256>>>();
    ou_scan_kernel<<<NB, 256>>>(t, x0, z, out);
}